// round 16
// baseline (speedup 1.0000x reference)
#include <cuda_runtime.h>
#include <cuda_fp16.h>
#include <math.h>

#define MAXN 20000
#define MAXE 640000
#define NBATCH 8
#define FEAT 704            // 11 * 64 features per node
#define FEAT4 176           // FEAT / 4
#define N16 (MAXN * 16)

// ---------------- scratch (static device allocations) ----------------------
__device__ int    g_deg[MAXN];
__device__ float  g_dinv[MAXN];
__device__ int    g_rowptr[MAXN + 1];
__device__ int    g_cursor[MAXN];
__device__ int    g_bsum[32];
__device__ int2   g_edges[MAXE];           // (src, fp32-w bits), CSR by dest

// level-1: fp32 state + fp16 mirrors (unscaled, 128B rows)
__device__ float4 g_F1a[N16];
__device__ float4 g_F1b[N16];
__device__ float4 g_snap1[N16];
__device__ uint2  g_Mx [N16];              // fp16 mirror of x
__device__ uint2  g_M1a[N16];
__device__ uint2  g_M1b[N16];

// level-2: three independent 64-ch band cascades (bands 0..2), sliced buffers
__device__ float4 g_F2a[3 * N16];          // slot0 (holds seeds) per band
__device__ float4 g_F2b[3 * N16];          // slot1 per band
__device__ uint2  g_M2a[3 * N16];          // fp16 mirrors slot0
__device__ uint2  g_M2b[3 * N16];          // fp16 mirrors slot1
__device__ float4 g_snap2[3 * N16];

__device__ float4 g_feats[MAXN * 176];     // per-node features (N x 704)
__device__ int    g_start[NBATCH + 1];
__device__ double g_acc[4 * NBATCH * FEAT];

// ---------------- helpers ----------------------------------------------------
__device__ __forceinline__ float4 u2_to_f4(uint2 p) {
    float2 a = __half22float2(*reinterpret_cast<const __half2*>(&p.x));
    float2 b = __half22float2(*reinterpret_cast<const __half2*>(&p.y));
    return make_float4(a.x, a.y, b.x, b.y);
}
__device__ __forceinline__ uint2 f4_to_u2(float4 v) {
    __half2 a = __floats2half2_rn(v.x, v.y);
    __half2 b = __floats2half2_rn(v.z, v.w);
    uint2 p;
    p.x = *reinterpret_cast<unsigned*>(&a);
    p.y = *reinterpret_cast<unsigned*>(&b);
    return p;
}

// ---------------- setup kernels ---------------------------------------------
__global__ void k_init(const int* __restrict__ batch, int n) {
    int i = blockIdx.x * blockDim.x + threadIdx.x;
    if (i < n) {
        g_deg[i] = 1; g_cursor[i] = 0;                 // deg incl. self-loop
        int b = batch[i];
        int pb = (i == 0) ? -1 : batch[i - 1];
        for (int k = pb + 1; k <= b; ++k) g_start[k] = i;
        if (i == n - 1)
            for (int k = b + 1; k <= NBATCH; ++k) g_start[k] = n;
    }
    if (i < 4 * NBATCH * FEAT) g_acc[i] = 0.0;
}

// x-prep: feats col 0 + fp16 mirror of x (depends only on x; runs early)
__global__ void k_xprep(const float4* __restrict__ x4, int n) {
    int j = blockIdx.x * blockDim.x + threadIdx.x;
    if (j >= n * 16) return;
    float4 f = x4[j];
    g_feats[(j >> 4) * FEAT4 + (j & 15)] = f;
    g_Mx[j] = f4_to_u2(f);
}

__global__ void k_count(const int* __restrict__ col, int e) {
    int i = blockIdx.x * blockDim.x + threadIdx.x;
    if (i < e) atomicAdd(&g_deg[col[i]], 1);
}

// parallel scan A: per-block exclusive scans over (deg-1); also computes dinv
__global__ void k_scanA(int n) {
    int tid = threadIdx.x;
    int i = blockIdx.x * 1024 + tid;
    int v = 0;
    if (i < n) {
        int d = g_deg[i];
        g_dinv[i] = rsqrtf((float)d);
        v = d - 1;                                     // self-loops analytic
    }
    int lane = tid & 31, wid = tid >> 5;
    int inc = v;
    #pragma unroll
    for (int o = 1; o < 32; o <<= 1) {
        int u = __shfl_up_sync(0xffffffffu, inc, o);
        if (lane >= o) inc += u;
    }
    __shared__ int ws[32];
    if (lane == 31) ws[wid] = inc;
    __syncthreads();
    if (wid == 0) {
        int w = ws[lane];
        int wi = w;
        #pragma unroll
        for (int o = 1; o < 32; o <<= 1) {
            int u = __shfl_up_sync(0xffffffffu, wi, o);
            if (lane >= o) wi += u;
        }
        ws[lane] = wi - w;
    }
    __syncthreads();
    int exc = inc - v + ws[wid];
    if (i < n) g_rowptr[i] = exc;                      // local exclusive
    if (tid == 1023) g_bsum[blockIdx.x] = exc + v;
}
// merged scan B+C: every block computes its own offset from g_bsum (<=32)
__global__ void k_scanC(int nbk, int e, int n) {
    __shared__ int off;
    if (threadIdx.x < 32) {
        int v = (threadIdx.x < nbk) ? g_bsum[threadIdx.x] : 0;
        int inc = v;
        #pragma unroll
        for (int o = 1; o < 32; o <<= 1) {
            int u = __shfl_up_sync(0xffffffffu, inc, o);
            if ((threadIdx.x & 31) >= o) inc += u;
        }
        if ((int)threadIdx.x == (int)blockIdx.x) off = inc - v;  // exclusive
    }
    if (blockIdx.x == 0 && threadIdx.x == 0) g_rowptr[n] = e;
    __syncthreads();
    int i = blockIdx.x * 1024 + threadIdx.x;
    if (i < n) g_rowptr[i] += off;
}

// fill CSR edges (src, fp32 w) only
__global__ void k_fill(const int* __restrict__ row, const int* __restrict__ col,
                       int e) {
    int i = blockIdx.x * blockDim.x + threadIdx.x;
    if (i >= e) return;
    int r = row[i], c = col[i];
    float w = g_dinv[r] * g_dinv[c];
    int pos = g_rowptr[c] + atomicAdd(&g_cursor[c], 1);
    g_edges[pos] = make_int2(r, __float_as_int(w));
}

// ---------------- generic 64-ch diffusion step (16 thr/node, uint2 gather) -
// o = 0.5*(h + sum_e w_e*h16_src + dinv^2*h)
// wstate:     write o to (Fout, Mout)
// snap_save:  snap = o
// emit_col>=0 (exclusive with snap_save): d=|o-snap| -> feats block emit_col;
//             optional seed (seedF/seedM != null); refresh: snap = o
__global__ void k_gstep(const uint2* __restrict__ Mh, const float4* __restrict__ Hs,
                        float4* __restrict__ Fout, uint2* __restrict__ Mout,
                        float4* __restrict__ snap, float4* __restrict__ seedF,
                        uint2* __restrict__ seedM,
                        int n, int snap_save, int emit_col, int refresh, int wstate) {
    int v = blockIdx.x * blockDim.y + threadIdx.y;
    if (v >= n) return;
    int tx = threadIdx.x;                   // 0..15 : 4 channels
    int beg = g_rowptr[v], end = g_rowptr[v + 1];
    float4 acc = make_float4(0.f, 0.f, 0.f, 0.f);
    int e = beg;
    for (; e + 3 < end; e += 4) {
        int2 e0 = g_edges[e],     e1 = g_edges[e + 1];
        int2 e2 = g_edges[e + 2], e3 = g_edges[e + 3];
        float w0 = __int_as_float(e0.y), w1 = __int_as_float(e1.y);
        float w2 = __int_as_float(e2.y), w3 = __int_as_float(e3.y);
        float4 a = u2_to_f4(Mh[e0.x * 16 + tx]);
        float4 b = u2_to_f4(Mh[e1.x * 16 + tx]);
        float4 c = u2_to_f4(Mh[e2.x * 16 + tx]);
        float4 d = u2_to_f4(Mh[e3.x * 16 + tx]);
        acc.x += w0 * a.x + w1 * b.x + w2 * c.x + w3 * d.x;
        acc.y += w0 * a.y + w1 * b.y + w2 * c.y + w3 * d.y;
        acc.z += w0 * a.z + w1 * b.z + w2 * c.z + w3 * d.z;
        acc.w += w0 * a.w + w1 * b.w + w2 * c.w + w3 * d.w;
    }
    for (; e < end; ++e) {
        int2 e0 = g_edges[e];
        float w0 = __int_as_float(e0.y);
        float4 a = u2_to_f4(Mh[e0.x * 16 + tx]);
        acc.x += w0 * a.x; acc.y += w0 * a.y; acc.z += w0 * a.z; acc.w += w0 * a.w;
    }
    float dv = g_dinv[v];
    float sl = dv * dv;
    float4 h = Hs[v * 16 + tx];
    float4 o = make_float4(0.5f * (h.x + acc.x + sl * h.x),
                           0.5f * (h.y + acc.y + sl * h.y),
                           0.5f * (h.z + acc.z + sl * h.z),
                           0.5f * (h.w + acc.w + sl * h.w));
    if (wstate) {
        Fout[v * 16 + tx] = o;
        Mout[v * 16 + tx] = f4_to_u2(o);
    }
    if (snap_save) {
        snap[v * 16 + tx] = o;
    } else if (emit_col >= 0) {
        float4 p = snap[v * 16 + tx];
        float4 d4 = make_float4(fabsf(o.x - p.x), fabsf(o.y - p.y),
                                fabsf(o.z - p.z), fabsf(o.w - p.w));
        g_feats[v * FEAT4 + emit_col * 16 + tx] = d4;
        if (seedF) {
            seedF[v * 16 + tx] = d4;
            seedM[v * 16 + tx] = f4_to_u2(d4);
        }
        if (refresh) snap[v * 16 + tx] = o;
    }
}

// ---------------- raw moments over feature range [f0, f1) -------------------
#define MSLICE 32
__global__ void k_moments(int f0, int f1) {
    int f = f0 + blockIdx.x * blockDim.x + threadIdx.x;
    if (f >= f1) return;
    int b = blockIdx.y;
    int sl = blockIdx.z;
    int s = g_start[b], t = g_start[b + 1];
    int len = t - s;
    int i0 = s + (int)((long long)len * sl / MSLICE);
    int i1 = s + (int)((long long)len * (sl + 1) / MSLICE);
    if (i0 >= i1) return;
    const float* feats = (const float*)g_feats;
    float s1 = 0.f, s2 = 0.f, s3 = 0.f, s4 = 0.f;
    for (int i = i0; i < i1; ++i) {
        float v = feats[(size_t)i * FEAT + f];
        float v2 = v * v;
        s1 += v; s2 += v2; s3 += v2 * v; s4 += v2 * v2;
    }
    atomicAdd(&g_acc[(0 * NBATCH + b) * FEAT + f], (double)s1);
    atomicAdd(&g_acc[(1 * NBATCH + b) * FEAT + f], (double)s2);
    atomicAdd(&g_acc[(2 * NBATCH + b) * FEAT + f], (double)s3);
    atomicAdd(&g_acc[(3 * NBATCH + b) * FEAT + f], (double)s4);
}

__global__ void k_finalize(const float* __restrict__ wav, float* __restrict__ out,
                           int out_size) {
    int idx = blockIdx.x * blockDim.x + threadIdx.x;
    if (idx < NBATCH * FEAT) {
        int b = idx / FEAT, f = idx % FEAT;
        int c = g_start[b + 1] - g_start[b];
        double cnt = (c > 0) ? (double)c : 1.0;
        double m  = g_acc[(0 * NBATCH + b) * FEAT + f] / cnt;
        double e2 = g_acc[(1 * NBATCH + b) * FEAT + f] / cnt;
        double e3 = g_acc[(2 * NBATCH + b) * FEAT + f] / cnt;
        double e4 = g_acc[(3 * NBATCH + b) * FEAT + f] / cnt;
        double var = e2 - m * m;
        double m3 = e3 - 3.0 * m * e2 + 2.0 * m * m * m;
        double m4 = e4 - 4.0 * m * e3 + 6.0 * m * m * e2 - 3.0 * m * m * m * m;
        float skew, kurt;
        if (var > 0.0) {
            skew = (float)(m3 / (var * sqrt(var)));
            kurt = (float)(m4 / (var * var));
        } else { skew = 0.f; kurt = -3.f; }
        float* row = out + (size_t)b * (4 * FEAT);
        row[f] = (float)m;
        row[FEAT + f] = (float)var;
        row[2 * FEAT + f] = skew;
        row[3 * FEAT + f] = kurt;
    } else {
        int t = idx - NBATCH * FEAT;
        if (t < 68 && out_size >= NBATCH * 4 * FEAT + 68)
            out[NBATCH * 4 * FEAT + t] = wav[t];
    }
}

// ---------------- driver -----------------------------------------------------
extern "C" void kernel_launch(void* const* d_in, const int* in_sizes, int n_in,
                              void* d_out, int out_size) {
    const float* x   = (const float*)d_in[0];
    const int*   ei  = (const int*)d_in[1];
    const int*   bat = (const int*)d_in[2];
    const float* wav = (const float*)d_in[3];
    float* out = (float*)d_out;

    int E = in_sizes[1] / 2;
    int N = in_sizes[2];
    if (N > MAXN) N = MAXN;
    if (E > MAXE) E = MAXE;
    const int* row = ei;
    const int* col = ei + E;

    void* p;
    cudaGetSymbolAddress(&p, g_F1a);   float4* F1a = (float4*)p;
    cudaGetSymbolAddress(&p, g_F1b);   float4* F1b = (float4*)p;
    cudaGetSymbolAddress(&p, g_snap1); float4* S1  = (float4*)p;
    cudaGetSymbolAddress(&p, g_Mx);    uint2*  Mx  = (uint2*)p;
    cudaGetSymbolAddress(&p, g_M1a);   uint2*  M1a = (uint2*)p;
    cudaGetSymbolAddress(&p, g_M1b);   uint2*  M1b = (uint2*)p;
    cudaGetSymbolAddress(&p, g_F2a);   float4* F2a = (float4*)p;
    cudaGetSymbolAddress(&p, g_F2b);   float4* F2b = (float4*)p;
    cudaGetSymbolAddress(&p, g_M2a);   uint2*  M2a = (uint2*)p;
    cudaGetSymbolAddress(&p, g_M2b);   uint2*  M2b = (uint2*)p;
    cudaGetSymbolAddress(&p, g_snap2); float4* S2  = (float4*)p;

    // per-band buffer slices
    float4* BF[3][2]; uint2* BM[3][2]; float4* BS[3];
    for (int k = 0; k < 3; ++k) {
        BF[k][0] = F2a + (size_t)k * N16;  BF[k][1] = F2b + (size_t)k * N16;
        BM[k][0] = M2a + (size_t)k * N16;  BM[k][1] = M2b + (size_t)k * N16;
        BS[k] = S2 + (size_t)k * N16;
    }

    // Streams/events created ONCE on the first call (the correctness run);
    // no driver-side allocation during graph capture, identical sequence per call.
    static cudaStream_t sT = 0, sB0 = 0, sB1 = 0;
    static cudaEvent_t evRoot = 0, ev2 = 0, ev4 = 0, ev8 = 0, evT = 0,
                       evB0 = 0, evB1 = 0, evX = 0, evM1 = 0;
    if (sT == 0) {
        cudaStreamCreateWithFlags(&sT,  cudaStreamNonBlocking);
        cudaStreamCreateWithFlags(&sB0, cudaStreamNonBlocking);
        cudaStreamCreateWithFlags(&sB1, cudaStreamNonBlocking);
        cudaEventCreateWithFlags(&evRoot, cudaEventDisableTiming);
        cudaEventCreateWithFlags(&ev2,  cudaEventDisableTiming);
        cudaEventCreateWithFlags(&ev4,  cudaEventDisableTiming);
        cudaEventCreateWithFlags(&ev8,  cudaEventDisableTiming);
        cudaEventCreateWithFlags(&evT,  cudaEventDisableTiming);
        cudaEventCreateWithFlags(&evB0, cudaEventDisableTiming);
        cudaEventCreateWithFlags(&evB1, cudaEventDisableTiming);
        cudaEventCreateWithFlags(&evX,  cudaEventDisableTiming);
        cudaEventCreateWithFlags(&evM1, cudaEventDisableTiming);
    }

    // --- setup ---
    // Fork sB0 off the (possibly captured) origin stream FIRST, then run
    // x-prep there concurrently with the edge-side setup chain.
    cudaEventRecord(evRoot, 0);
    cudaStreamWaitEvent(sB0, evRoot, 0);
    k_xprep<<<(N * 16 + 255) / 256, 256, 0, sB0>>>((const float4*)x, N);
    cudaEventRecord(evX, sB0);

    int initN = (N > 4 * NBATCH * FEAT) ? N : 4 * NBATCH * FEAT;
    int nbk = (N + 1023) / 1024;
    k_init<<<(initN + 255) / 256, 256>>>(bat, N);
    k_count<<<(E + 255) / 256, 256>>>(col, E);
    k_scanA<<<nbk, 1024>>>(N);
    k_scanC<<<nbk, 1024>>>(nbk, E, N);
    k_fill<<<(E + 255) / 256, 256>>>(row, col, E);
    cudaStreamWaitEvent(0, evX, 0);        // t=1 gathers from Mx

    dim3 blk(16, 16);
    int grd = (N + 15) / 16;

    // --- level-1 cascade t = 1..8 (main stream) ---
    // t=1: snap save; t=2/4/8: emit cols 1/2/3 + seed band 0/1/2 + refresh.
    for (int t = 1; t <= 8; ++t) {
        const uint2*  inh = (t == 1) ? Mx : ((t & 1) ? M1b : M1a);
        const float4* ins = (t == 1) ? (const float4*)x : ((t & 1) ? F1b : F1a);
        float4* outs = (t & 1) ? F1a : F1b;
        uint2*  outh = (t & 1) ? M1a : M1b;
        int snap_save = (t == 1);
        int emit = -1; float4* sf = 0; uint2* sm = 0;
        if (t == 2) { emit = 1; sf = BF[0][0]; sm = BM[0][0]; }
        if (t == 4) { emit = 2; sf = BF[1][0]; sm = BM[1][0]; }
        if (t == 8) { emit = 3; sf = BF[2][0]; sm = BM[2][0]; }
        k_gstep<<<grd, blk>>>(inh, ins, outs, outh, S1, sf, sm,
                              N, snap_save, emit, (emit >= 0), 1);
        if (t == 2) cudaEventRecord(ev2, 0);
        if (t == 4) cudaEventRecord(ev4, 0);
    }
    cudaEventRecord(ev8, 0);

    // level-1 tail t=9..16 on sT, then early moments over feats cols 0..4
    cudaStreamWaitEvent(sT, ev8, 0);
    for (int t = 9; t <= 16; ++t) {
        const uint2*  inh = (t & 1) ? M1b : M1a;
        const float4* ins = (t & 1) ? F1b : F1a;
        float4* outs = (t & 1) ? F1a : F1b;
        uint2*  outh = (t & 1) ? M1a : M1b;
        int emit = (t == 16) ? 4 : -1;
        k_gstep<<<grd, blk, 0, sT>>>(inh, ins, outs, outh, S1, 0, 0,
                                     N, 0, emit, 0, (t < 16) ? 1 : 0);
    }
    cudaEventRecord(evT, sT);
    dim3 mg1((320 + 127) / 128, NBATCH, MSLICE);
    k_moments<<<mg1, 128, 0, sT>>>(0, 320);        // cols 0..4 (L1 branch)
    cudaEventRecord(evM1, sT);

    // --- band cascades: 16 steps each, 64 ch ---
    // band0 (sB0, after L1 t=2): snap@2; emit col5@4, col6@8, col8@16
    // band1 (sB1, after L1 t=4): snap@4; emit col7@8, col9@16
    // band2 (main, after L1 t=8): snap@8; emit col10@16
    struct Sched { int snapu; int eu[3]; int ec[3]; };
    Sched sc[3] = {
        {2, {4, 8, 16}, {5, 6, 8}},
        {4, {8, 16, -1}, {7, 9, -1}},
        {8, {16, -1, -1}, {10, -1, -1}},
    };
    cudaStream_t bstr[3] = {sB0, sB1, 0};
    cudaStreamWaitEvent(sB0, ev2, 0);
    cudaStreamWaitEvent(sB1, ev4, 0);
    for (int k = 0; k < 3; ++k) {
        for (int u = 1; u <= 16; ++u) {
            const uint2*  inh = BM[k][1 - (u & 1)];
            const float4* ins = BF[k][1 - (u & 1)];
            float4* outs = BF[k][u & 1];
            uint2*  outh = BM[k][u & 1];
            int snap_save = (u == sc[k].snapu);
            int emit = -1;
            for (int q = 0; q < 3; ++q)
                if (sc[k].eu[q] == u) emit = sc[k].ec[q];
            int refresh = (emit >= 0 && u < 16);
            int wstate = (u < 16);
            k_gstep<<<grd, blk, 0, bstr[k]>>>(inh, ins, outs, outh, BS[k], 0, 0,
                                              N, snap_save, emit, refresh, wstate);
        }
    }
    cudaEventRecord(evB0, sB0);
    cudaEventRecord(evB1, sB1);

    // join: remaining moments need feats cols 5..10 from all bands + part1 done
    cudaStreamWaitEvent(0, evB0, 0);
    cudaStreamWaitEvent(0, evB1, 0);
    cudaStreamWaitEvent(0, evM1, 0);

    // --- batch statistics part 2 (cols 5..10) + finalize (main stream) ---
    dim3 mg2((FEAT - 320 + 127) / 128, NBATCH, MSLICE);
    k_moments<<<mg2, 128>>>(320, FEAT);
    int fin = NBATCH * FEAT + 68;
    k_finalize<<<(fin + 255) / 256, 256>>>(wav, out, out_size);
}

// round 17
// speedup vs baseline: 1.0071x; 1.0071x over previous
#include <cuda_runtime.h>
#include <cuda_fp16.h>
#include <math.h>

#define MAXN 20000
#define MAXE 640000
#define NBATCH 8
#define FEAT 704            // 11 * 64 features per node
#define FEAT4 176           // FEAT / 4
#define N16 (MAXN * 16)

// ---------------- scratch (static device allocations) ----------------------
__device__ int    g_deg[MAXN];
__device__ float  g_dinv[MAXN];
__device__ int    g_rowptr[MAXN + 1];
__device__ int    g_cursor[MAXN];
__device__ int    g_bsum[32];
__device__ int2   g_edges[MAXE];           // (src, fp32-w bits), CSR by dest

// level-1: fp32 state + fp16 mirrors (unscaled, 128B rows)
__device__ float4 g_F1a[N16];
__device__ float4 g_F1b[N16];
__device__ float4 g_snap1[N16];
__device__ uint2  g_Mx [N16];              // fp16 mirror of x
__device__ uint2  g_M1a[N16];
__device__ uint2  g_M1b[N16];

// level-2: three independent 64-ch band cascades (bands 0..2), sliced buffers
__device__ float4 g_F2a[3 * N16];          // slot0 (holds seeds) per band
__device__ float4 g_F2b[3 * N16];          // slot1 per band
__device__ uint2  g_M2a[3 * N16];          // fp16 mirrors slot0
__device__ uint2  g_M2b[3 * N16];          // fp16 mirrors slot1
__device__ float4 g_snap2[3 * N16];

__device__ float4 g_feats[MAXN * 176];     // per-node features (N x 704)
__device__ int    g_start[NBATCH + 1];
__device__ double g_acc[4 * NBATCH * FEAT];

// ---------------- helpers ----------------------------------------------------
__device__ __forceinline__ float4 u2_to_f4(uint2 p) {
    float2 a = __half22float2(*reinterpret_cast<const __half2*>(&p.x));
    float2 b = __half22float2(*reinterpret_cast<const __half2*>(&p.y));
    return make_float4(a.x, a.y, b.x, b.y);
}
__device__ __forceinline__ uint2 f4_to_u2(float4 v) {
    __half2 a = __floats2half2_rn(v.x, v.y);
    __half2 b = __floats2half2_rn(v.z, v.w);
    uint2 p;
    p.x = *reinterpret_cast<unsigned*>(&a);
    p.y = *reinterpret_cast<unsigned*>(&b);
    return p;
}

// ---------------- setup kernels ---------------------------------------------
__global__ void k_init(const int* __restrict__ batch, int n) {
    int i = blockIdx.x * blockDim.x + threadIdx.x;
    if (i < n) {
        g_deg[i] = 1; g_cursor[i] = 0;                 // deg incl. self-loop
        int b = batch[i];
        int pb = (i == 0) ? -1 : batch[i - 1];
        for (int k = pb + 1; k <= b; ++k) g_start[k] = i;
        if (i == n - 1)
            for (int k = b + 1; k <= NBATCH; ++k) g_start[k] = n;
    }
    if (i < 4 * NBATCH * FEAT) g_acc[i] = 0.0;
}

__global__ void k_count(const int* __restrict__ col, int e) {
    int i = blockIdx.x * blockDim.x + threadIdx.x;
    if (i < e) atomicAdd(&g_deg[col[i]], 1);
}

// parallel scan A: per-block exclusive scans over (deg-1); also computes dinv
__global__ void k_scanA(int n) {
    int tid = threadIdx.x;
    int i = blockIdx.x * 1024 + tid;
    int v = 0;
    if (i < n) {
        int d = g_deg[i];
        g_dinv[i] = rsqrtf((float)d);
        v = d - 1;                                     // self-loops analytic
    }
    int lane = tid & 31, wid = tid >> 5;
    int inc = v;
    #pragma unroll
    for (int o = 1; o < 32; o <<= 1) {
        int u = __shfl_up_sync(0xffffffffu, inc, o);
        if (lane >= o) inc += u;
    }
    __shared__ int ws[32];
    if (lane == 31) ws[wid] = inc;
    __syncthreads();
    if (wid == 0) {
        int w = ws[lane];
        int wi = w;
        #pragma unroll
        for (int o = 1; o < 32; o <<= 1) {
            int u = __shfl_up_sync(0xffffffffu, wi, o);
            if (lane >= o) wi += u;
        }
        ws[lane] = wi - w;
    }
    __syncthreads();
    int exc = inc - v + ws[wid];
    if (i < n) g_rowptr[i] = exc;                      // local exclusive
    if (tid == 1023) g_bsum[blockIdx.x] = exc + v;
}
// merged scan B+C: every block computes its own offset from g_bsum (<=32)
__global__ void k_scanC(int nbk, int e, int n) {
    __shared__ int off;
    if (threadIdx.x < 32) {
        int v = (threadIdx.x < nbk) ? g_bsum[threadIdx.x] : 0;
        int inc = v;
        #pragma unroll
        for (int o = 1; o < 32; o <<= 1) {
            int u = __shfl_up_sync(0xffffffffu, inc, o);
            if ((threadIdx.x & 31) >= o) inc += u;
        }
        if ((int)threadIdx.x == (int)blockIdx.x) off = inc - v;  // exclusive
    }
    if (blockIdx.x == 0 && threadIdx.x == 0) g_rowptr[n] = e;
    __syncthreads();
    int i = blockIdx.x * 1024 + threadIdx.x;
    if (i < n) g_rowptr[i] += off;
}

// fill CSR edges (src, fp32 w); build fp16 x mirror; copy x into feats blk 0
__global__ void k_fill(const int* __restrict__ row, const int* __restrict__ col,
                       const float4* __restrict__ x4, int e, int n) {
    int i = blockIdx.x * blockDim.x + threadIdx.x;
    if (i < e) {
        int r = row[i], c = col[i];
        float w = g_dinv[r] * g_dinv[c];
        int pos = g_rowptr[c] + atomicAdd(&g_cursor[c], 1);
        g_edges[pos] = make_int2(r, __float_as_int(w));
    } else {
        int j = i - e;
        if (j < n * 16) {
            float4 f = x4[j];
            g_feats[(j >> 4) * FEAT4 + (j & 15)] = f;
            g_Mx[j] = f4_to_u2(f);
        }
    }
}

// ---------------- generic 64-ch diffusion step (16 thr/node, uint2 gather) -
// o = 0.5*(h + sum_e w_e*h16_src + dinv^2*h)
// wstate:     write o to (Fout, Mout)
// snap_save:  snap = o
// emit_col>=0 (exclusive with snap_save): d=|o-snap| -> feats block emit_col;
//             optional seed (seedF/seedM != null); refresh: snap = o
__global__ void k_gstep(const uint2* __restrict__ Mh, const float4* __restrict__ Hs,
                        float4* __restrict__ Fout, uint2* __restrict__ Mout,
                        float4* __restrict__ snap, float4* __restrict__ seedF,
                        uint2* __restrict__ seedM,
                        int n, int snap_save, int emit_col, int refresh, int wstate) {
    int v = blockIdx.x * blockDim.y + threadIdx.y;
    if (v >= n) return;
    int tx = threadIdx.x;                   // 0..15 : 4 channels
    int beg = g_rowptr[v], end = g_rowptr[v + 1];
    float4 acc = make_float4(0.f, 0.f, 0.f, 0.f);
    int e = beg;
    for (; e + 3 < end; e += 4) {
        int2 e0 = g_edges[e],     e1 = g_edges[e + 1];
        int2 e2 = g_edges[e + 2], e3 = g_edges[e + 3];
        float w0 = __int_as_float(e0.y), w1 = __int_as_float(e1.y);
        float w2 = __int_as_float(e2.y), w3 = __int_as_float(e3.y);
        float4 a = u2_to_f4(Mh[e0.x * 16 + tx]);
        float4 b = u2_to_f4(Mh[e1.x * 16 + tx]);
        float4 c = u2_to_f4(Mh[e2.x * 16 + tx]);
        float4 d = u2_to_f4(Mh[e3.x * 16 + tx]);
        acc.x += w0 * a.x + w1 * b.x + w2 * c.x + w3 * d.x;
        acc.y += w0 * a.y + w1 * b.y + w2 * c.y + w3 * d.y;
        acc.z += w0 * a.z + w1 * b.z + w2 * c.z + w3 * d.z;
        acc.w += w0 * a.w + w1 * b.w + w2 * c.w + w3 * d.w;
    }
    for (; e < end; ++e) {
        int2 e0 = g_edges[e];
        float w0 = __int_as_float(e0.y);
        float4 a = u2_to_f4(Mh[e0.x * 16 + tx]);
        acc.x += w0 * a.x; acc.y += w0 * a.y; acc.z += w0 * a.z; acc.w += w0 * a.w;
    }
    float dv = g_dinv[v];
    float sl = dv * dv;
    float4 h = Hs[v * 16 + tx];
    float4 o = make_float4(0.5f * (h.x + acc.x + sl * h.x),
                           0.5f * (h.y + acc.y + sl * h.y),
                           0.5f * (h.z + acc.z + sl * h.z),
                           0.5f * (h.w + acc.w + sl * h.w));
    if (wstate) {
        Fout[v * 16 + tx] = o;
        Mout[v * 16 + tx] = f4_to_u2(o);
    }
    if (snap_save) {
        snap[v * 16 + tx] = o;
    } else if (emit_col >= 0) {
        float4 p = snap[v * 16 + tx];
        float4 d4 = make_float4(fabsf(o.x - p.x), fabsf(o.y - p.y),
                                fabsf(o.z - p.z), fabsf(o.w - p.w));
        g_feats[v * FEAT4 + emit_col * 16 + tx] = d4;
        if (seedF) {
            seedF[v * 16 + tx] = d4;
            seedM[v * 16 + tx] = f4_to_u2(d4);
        }
        if (refresh) snap[v * 16 + tx] = o;
    }
}

// ---------------- raw moments (fp32 partials, fp64 merge) ------------------
#define MSLICE 32
__global__ void k_moments() {
    int f = blockIdx.x * blockDim.x + threadIdx.x;
    if (f >= FEAT) return;
    int b = blockIdx.y;
    int sl = blockIdx.z;
    int s = g_start[b], t = g_start[b + 1];
    int len = t - s;
    int i0 = s + (int)((long long)len * sl / MSLICE);
    int i1 = s + (int)((long long)len * (sl + 1) / MSLICE);
    if (i0 >= i1) return;
    const float* feats = (const float*)g_feats;
    float s1 = 0.f, s2 = 0.f, s3 = 0.f, s4 = 0.f;
    for (int i = i0; i < i1; ++i) {
        float v = feats[(size_t)i * FEAT + f];
        float v2 = v * v;
        s1 += v; s2 += v2; s3 += v2 * v; s4 += v2 * v2;
    }
    atomicAdd(&g_acc[(0 * NBATCH + b) * FEAT + f], (double)s1);
    atomicAdd(&g_acc[(1 * NBATCH + b) * FEAT + f], (double)s2);
    atomicAdd(&g_acc[(2 * NBATCH + b) * FEAT + f], (double)s3);
    atomicAdd(&g_acc[(3 * NBATCH + b) * FEAT + f], (double)s4);
}

__global__ void k_finalize(const float* __restrict__ wav, float* __restrict__ out,
                           int out_size) {
    int idx = blockIdx.x * blockDim.x + threadIdx.x;
    if (idx < NBATCH * FEAT) {
        int b = idx / FEAT, f = idx % FEAT;
        int c = g_start[b + 1] - g_start[b];
        double cnt = (c > 0) ? (double)c : 1.0;
        double m  = g_acc[(0 * NBATCH + b) * FEAT + f] / cnt;
        double e2 = g_acc[(1 * NBATCH + b) * FEAT + f] / cnt;
        double e3 = g_acc[(2 * NBATCH + b) * FEAT + f] / cnt;
        double e4 = g_acc[(3 * NBATCH + b) * FEAT + f] / cnt;
        double var = e2 - m * m;
        double m3 = e3 - 3.0 * m * e2 + 2.0 * m * m * m;
        double m4 = e4 - 4.0 * m * e3 + 6.0 * m * m * e2 - 3.0 * m * m * m * m;
        float skew, kurt;
        if (var > 0.0) {
            skew = (float)(m3 / (var * sqrt(var)));
            kurt = (float)(m4 / (var * var));
        } else { skew = 0.f; kurt = -3.f; }
        float* row = out + (size_t)b * (4 * FEAT);
        row[f] = (float)m;
        row[FEAT + f] = (float)var;
        row[2 * FEAT + f] = skew;
        row[3 * FEAT + f] = kurt;
    } else {
        int t = idx - NBATCH * FEAT;
        if (t < 68 && out_size >= NBATCH * 4 * FEAT + 68)
            out[NBATCH * 4 * FEAT + t] = wav[t];
    }
}

// ---------------- driver -----------------------------------------------------
extern "C" void kernel_launch(void* const* d_in, const int* in_sizes, int n_in,
                              void* d_out, int out_size) {
    const float* x   = (const float*)d_in[0];
    const int*   ei  = (const int*)d_in[1];
    const int*   bat = (const int*)d_in[2];
    const float* wav = (const float*)d_in[3];
    float* out = (float*)d_out;

    int E = in_sizes[1] / 2;
    int N = in_sizes[2];
    if (N > MAXN) N = MAXN;
    if (E > MAXE) E = MAXE;
    const int* row = ei;
    const int* col = ei + E;

    void* p;
    cudaGetSymbolAddress(&p, g_F1a);   float4* F1a = (float4*)p;
    cudaGetSymbolAddress(&p, g_F1b);   float4* F1b = (float4*)p;
    cudaGetSymbolAddress(&p, g_snap1); float4* S1  = (float4*)p;
    cudaGetSymbolAddress(&p, g_Mx);    uint2*  Mx  = (uint2*)p;
    cudaGetSymbolAddress(&p, g_M1a);   uint2*  M1a = (uint2*)p;
    cudaGetSymbolAddress(&p, g_M1b);   uint2*  M1b = (uint2*)p;
    cudaGetSymbolAddress(&p, g_F2a);   float4* F2a = (float4*)p;
    cudaGetSymbolAddress(&p, g_F2b);   float4* F2b = (float4*)p;
    cudaGetSymbolAddress(&p, g_M2a);   uint2*  M2a = (uint2*)p;
    cudaGetSymbolAddress(&p, g_M2b);   uint2*  M2b = (uint2*)p;
    cudaGetSymbolAddress(&p, g_snap2); float4* S2  = (float4*)p;

    // per-band buffer slices
    float4* BF[3][2]; uint2* BM[3][2]; float4* BS[3];
    for (int k = 0; k < 3; ++k) {
        BF[k][0] = F2a + (size_t)k * N16;  BF[k][1] = F2b + (size_t)k * N16;
        BM[k][0] = M2a + (size_t)k * N16;  BM[k][1] = M2b + (size_t)k * N16;
        BS[k] = S2 + (size_t)k * N16;
    }

    // Streams/events created ONCE on the first call (the correctness run);
    // no driver-side allocation during graph capture, identical sequence per call.
    static cudaStream_t sT = 0, sB0 = 0, sB1 = 0;
    static cudaEvent_t ev2 = 0, ev4 = 0, ev8 = 0, evT = 0, evB0 = 0, evB1 = 0;
    if (sT == 0) {
        cudaStreamCreateWithFlags(&sT,  cudaStreamNonBlocking);
        cudaStreamCreateWithFlags(&sB0, cudaStreamNonBlocking);
        cudaStreamCreateWithFlags(&sB1, cudaStreamNonBlocking);
        cudaEventCreateWithFlags(&ev2,  cudaEventDisableTiming);
        cudaEventCreateWithFlags(&ev4,  cudaEventDisableTiming);
        cudaEventCreateWithFlags(&ev8,  cudaEventDisableTiming);
        cudaEventCreateWithFlags(&evT,  cudaEventDisableTiming);
        cudaEventCreateWithFlags(&evB0, cudaEventDisableTiming);
        cudaEventCreateWithFlags(&evB1, cudaEventDisableTiming);
    }

    // --- setup (main stream) ---
    int initN = (N > 4 * NBATCH * FEAT) ? N : 4 * NBATCH * FEAT;
    int nbk = (N + 1023) / 1024;
    k_init<<<(initN + 255) / 256, 256>>>(bat, N);
    k_count<<<(E + 255) / 256, 256>>>(col, E);
    k_scanA<<<nbk, 1024>>>(N);
    k_scanC<<<nbk, 1024>>>(nbk, E, N);
    k_fill<<<(E + N * 16 + 255) / 256, 256>>>(row, col, (const float4*)x, E, N);

    dim3 blk(16, 16);
    int grd = (N + 15) / 16;

    // --- level-1 cascade t = 1..8 (main stream) ---
    // t=1: snap save; t=2/4/8: emit cols 1/2/3 + seed band 0/1/2 + refresh.
    for (int t = 1; t <= 8; ++t) {
        const uint2*  inh = (t == 1) ? Mx : ((t & 1) ? M1b : M1a);
        const float4* ins = (t == 1) ? (const float4*)x : ((t & 1) ? F1b : F1a);
        float4* outs = (t & 1) ? F1a : F1b;
        uint2*  outh = (t & 1) ? M1a : M1b;
        int snap_save = (t == 1);
        int emit = -1; float4* sf = 0; uint2* sm = 0;
        if (t == 2) { emit = 1; sf = BF[0][0]; sm = BM[0][0]; }
        if (t == 4) { emit = 2; sf = BF[1][0]; sm = BM[1][0]; }
        if (t == 8) { emit = 3; sf = BF[2][0]; sm = BM[2][0]; }
        k_gstep<<<grd, blk>>>(inh, ins, outs, outh, S1, sf, sm,
                              N, snap_save, emit, (emit >= 0), 1);
        if (t == 2) cudaEventRecord(ev2, 0);
        if (t == 4) cudaEventRecord(ev4, 0);
    }
    cudaEventRecord(ev8, 0);

    // level-1 tail t=9..16 on sT (independent of all band cascades)
    cudaStreamWaitEvent(sT, ev8, 0);
    for (int t = 9; t <= 16; ++t) {
        const uint2*  inh = (t & 1) ? M1b : M1a;
        const float4* ins = (t & 1) ? F1b : F1a;
        float4* outs = (t & 1) ? F1a : F1b;
        uint2*  outh = (t & 1) ? M1a : M1b;
        int emit = (t == 16) ? 4 : -1;
        k_gstep<<<grd, blk, 0, sT>>>(inh, ins, outs, outh, S1, 0, 0,
                                     N, 0, emit, 0, (t < 16) ? 1 : 0);
    }
    cudaEventRecord(evT, sT);

    // --- band cascades: 16 steps each, 64 ch ---
    // band0 (sB0, after L1 t=2): snap@2; emit col5@4, col6@8, col8@16
    // band1 (sB1, after L1 t=4): snap@4; emit col7@8, col9@16
    // band2 (main, after L1 t=8): snap@8; emit col10@16
    struct Sched { int snapu; int eu[3]; int ec[3]; };
    Sched sc[3] = {
        {2, {4, 8, 16}, {5, 6, 8}},
        {4, {8, 16, -1}, {7, 9, -1}},
        {8, {16, -1, -1}, {10, -1, -1}},
    };
    cudaStream_t bstr[3] = {sB0, sB1, 0};
    cudaStreamWaitEvent(sB0, ev2, 0);
    cudaStreamWaitEvent(sB1, ev4, 0);
    for (int k = 0; k < 3; ++k) {
        for (int u = 1; u <= 16; ++u) {
            const uint2*  inh = BM[k][1 - (u & 1)];
            const float4* ins = BF[k][1 - (u & 1)];
            float4* outs = BF[k][u & 1];
            uint2*  outh = BM[k][u & 1];
            int snap_save = (u == sc[k].snapu);
            int emit = -1;
            for (int q = 0; q < 3; ++q)
                if (sc[k].eu[q] == u) emit = sc[k].ec[q];
            int refresh = (emit >= 0 && u < 16);
            int wstate = (u < 16);
            k_gstep<<<grd, blk, 0, bstr[k]>>>(inh, ins, outs, outh, BS[k], 0, 0,
                                              N, snap_save, emit, refresh, wstate);
        }
    }
    cudaEventRecord(evB0, sB0);
    cudaEventRecord(evB1, sB1);

    // join: stats need feats from every branch
    cudaStreamWaitEvent(0, evT, 0);
    cudaStreamWaitEvent(0, evB0, 0);
    cudaStreamWaitEvent(0, evB1, 0);

    // --- batch statistics (main stream) ---
    dim3 mg((FEAT + 127) / 128, NBATCH, MSLICE);
    k_moments<<<mg, 128>>>();
    int fin = NBATCH * FEAT + 68;
    k_finalize<<<(fin + 255) / 256, 256>>>(wav, out, out_size);
}